// round 1
// baseline (speedup 1.0000x reference)
#include <cuda_runtime.h>
#include <cuda_bf16.h>

// Problem constants (fixed by the reference): OUT=64, IN=128.
#define OUT_DIM 64
#define IN_DIM 128
#define MAX_POOL 16384
#define MAX_EDGES 65536

// Scratch (allocation-free rule: __device__ globals)
__device__ int g_counts[MAX_POOL];
__device__ int g_offsets[MAX_POOL];
__device__ int g_cursor[MAX_POOL];
__device__ int g_sorted[MAX_EDGES];

// ---------------------------------------------------------------------------
// 1) zero counts
__global__ void zero_counts_kernel(int npool) {
    int i = blockIdx.x * blockDim.x + threadIdx.x;
    if (i < npool) g_counts[i] = 0;
}

// 2) histogram of edge indices
__global__ void hist_kernel(const int* __restrict__ idx, int n) {
    int i = blockIdx.x * blockDim.x + threadIdx.x;
    if (i < n) atomicAdd(&g_counts[idx[i]], 1);
}

// 3) single-block exclusive scan over npool bins (chunked Hillis-Steele)
__global__ void scan_kernel(int npool) {
    __shared__ int s[1024];
    __shared__ int s_carry;
    int tid = threadIdx.x;
    if (tid == 0) s_carry = 0;
    __syncthreads();
    for (int base = 0; base < npool; base += 1024) {
        int i = base + tid;
        int v = (i < npool) ? g_counts[i] : 0;
        s[tid] = v;
        __syncthreads();
        #pragma unroll
        for (int off = 1; off < 1024; off <<= 1) {
            int t = (tid >= off) ? s[tid - off] : 0;
            __syncthreads();
            s[tid] += t;
            __syncthreads();
        }
        int excl = s[tid] - v + s_carry;
        if (i < npool) {
            g_offsets[i] = excl;
            g_cursor[i]  = excl;
        }
        __syncthreads();
        if (tid == 1023) s_carry += s[1023];
        __syncthreads();
    }
}

// 4) scatter edge ids into grouped order
__global__ void scatter_kernel(const int* __restrict__ idx, int n) {
    int i = blockIdx.x * blockDim.x + threadIdx.x;
    if (i < n) {
        int p = atomicAdd(&g_cursor[idx[i]], 1);
        g_sorted[p] = i;
    }
}

// ---------------------------------------------------------------------------
// 5) compute: one CTA per pool entry. Load W (64x128 fp32 = 32 KB) into SMEM
//    once, register it with a stride-4 K interleave (thread (r,q) holds
//    W[r][q + 4j], j=0..31), then stream all edges of this group through it.
//    Per edge: x -> SMEM (coalesced 512 B), 32 FMAs/thread, 2-level shfl
//    reduction across the 4 q-lanes, relu+bias store.
__global__ __launch_bounds__(256) void compute_kernel(
    const float* __restrict__ x,      // [E, 128]
    const float* __restrict__ Wpool,  // [P, 64, 128]
    const float* __restrict__ bpool,  // [P, 64]
    float* __restrict__ out)          // [E, 64]
{
    int w = blockIdx.x;
    int cnt = g_counts[w];
    if (cnt == 0) return;

    __shared__ float sW[OUT_DIM * IN_DIM];
    __shared__ float sx[IN_DIM];

    int tid = threadIdx.x;

    // Coalesced W load: 8192 floats = 2048 float4, 256 threads x 8.
    const float4* Wg = reinterpret_cast<const float4*>(Wpool + (size_t)w * (OUT_DIM * IN_DIM));
    float4* sW4 = reinterpret_cast<float4*>(sW);
    #pragma unroll
    for (int i = 0; i < 8; i++)
        sW4[tid + 256 * i] = Wg[tid + 256 * i];
    __syncthreads();

    int r = tid >> 2;   // output row 0..63
    int q = tid & 3;    // K quadrant

    // Register the W row slice, interleaved stride-4 so the x SMEM read
    // pattern sx[q + 4j] is bank-conflict-free (4 distinct banks, 8-lane
    // broadcast across r within each warp).
    float wreg[32];
    #pragma unroll
    for (int j = 0; j < 32; j++)
        wreg[j] = sW[r * IN_DIM + q + 4 * j];

    float bias = bpool[(size_t)w * OUT_DIM + r];

    int start = g_offsets[w];
    for (int t = 0; t < cnt; t++) {
        int e = g_sorted[start + t];
        __syncthreads();                        // protect sx reuse
        if (tid < IN_DIM) sx[tid] = x[(size_t)e * IN_DIM + tid];
        __syncthreads();

        // 4 accumulators to break the FMA dependency chain.
        float a0 = 0.f, a1 = 0.f, a2 = 0.f, a3 = 0.f;
        #pragma unroll
        for (int j = 0; j < 32; j += 4) {
            a0 = fmaf(wreg[j + 0], sx[q + 4 * (j + 0)], a0);
            a1 = fmaf(wreg[j + 1], sx[q + 4 * (j + 1)], a1);
            a2 = fmaf(wreg[j + 2], sx[q + 4 * (j + 2)], a2);
            a3 = fmaf(wreg[j + 3], sx[q + 4 * (j + 3)], a3);
        }
        float acc = (a0 + a1) + (a2 + a3);
        acc += __shfl_xor_sync(0xffffffffu, acc, 1);
        acc += __shfl_xor_sync(0xffffffffu, acc, 2);
        if (q == 0) {
            float y = acc + bias;
            out[(size_t)e * OUT_DIM + r] = y > 0.f ? y : 0.f;
        }
    }
}

// ---------------------------------------------------------------------------
extern "C" void kernel_launch(void* const* d_in, const int* in_sizes, int n_in,
                              void* d_out, int out_size) {
    const float* x     = (const float*)d_in[0];  // [E,128,1]
    const int*   idx   = (const int*)d_in[1];    // [E]
    const float* Wpool = (const float*)d_in[2];  // [P,64,128]
    const float* bpool = (const float*)d_in[3];  // [P,64,1]
    float* out = (float*)d_out;                  // [E,64,1]

    int E     = in_sizes[1];
    int npool = in_sizes[3] / OUT_DIM;

    int eb = (E + 255) / 256;
    int pb = (npool + 255) / 256;

    zero_counts_kernel<<<pb, 256>>>(npool);
    hist_kernel<<<eb, 256>>>(idx, E);
    scan_kernel<<<1, 1024>>>(npool);
    scatter_kernel<<<eb, 256>>>(idx, E);
    compute_kernel<<<npool, 256>>>(x, Wpool, bpool, out);
}

// round 2
// speedup vs baseline: 1.2760x; 1.2760x over previous
#include <cuda_runtime.h>
#include <cuda_bf16.h>

#define OUT_DIM 64
#define IN_DIM 128
#define MAX_POOL 16384
#define MAX_EDGES 65536
#define CHUNK 8
// skewed smem row stride for x: quadrant q starts at word q*36 (conflict-free LDS.128)
#define XROW 144   // 4 quadrants * 36 words

__device__ int g_counts[MAX_POOL];
__device__ int g_offsets[MAX_POOL];
__device__ int g_cursor[MAX_POOL];
__device__ int g_sorted[MAX_EDGES];

// ---------------------------------------------------------------------------
__global__ void zero_counts_kernel(int npool) {
    int i = blockIdx.x * blockDim.x + threadIdx.x;
    if (i < npool) g_counts[i] = 0;
}

__global__ void hist_kernel(const int* __restrict__ idx, int n) {
    int i = blockIdx.x * blockDim.x + threadIdx.x;
    if (i < n) atomicAdd(&g_counts[idx[i]], 1);
}

// Hierarchical exclusive scan, one 1024-thread block, 2 barriers total.
__global__ void scan_kernel(int npool) {
    int tid = threadIdx.x;
    int per = (npool + 1023) >> 10;            // bins per thread (<=16)
    int lo = tid * per;
    int hi = min(lo + per, npool);

    int local[16];
    int sum = 0;
    for (int i = lo; i < hi; i++) { local[i - lo] = sum; sum += g_counts[i]; }

    int lane = tid & 31, wid = tid >> 5;
    int v = sum;
    #pragma unroll
    for (int o = 1; o < 32; o <<= 1) {
        int t = __shfl_up_sync(0xffffffffu, v, o);
        if (lane >= o) v += t;
    }
    __shared__ int ws[32];
    if (lane == 31) ws[wid] = v;               // inclusive warp totals
    __syncthreads();
    if (wid == 0) {
        int t = ws[lane];
        #pragma unroll
        for (int o = 1; o < 32; o <<= 1) {
            int u = __shfl_up_sync(0xffffffffu, t, o);
            if (lane >= o) t += u;
        }
        ws[lane] = t;                          // inclusive scan of warp totals
    }
    __syncthreads();
    int base = (v - sum) + (wid > 0 ? ws[wid - 1] : 0);
    for (int i = lo; i < hi; i++) {
        int off = base + local[i - lo];
        g_offsets[i] = off;
        g_cursor[i]  = off;
    }
}

__global__ void scatter_kernel(const int* __restrict__ idx, int n) {
    int i = blockIdx.x * blockDim.x + threadIdx.x;
    if (i < n) {
        int p = atomicAdd(&g_cursor[idx[i]], 1);
        g_sorted[p] = i;
    }
}

// ---------------------------------------------------------------------------
// Compute: one CTA per pool entry. W slice straight GMEM->registers
// (thread (r,q) holds W[r][q*32 .. q*32+31] as 8 float4, coalesced).
// Edge x vectors prefetched in chunks of 8 into skewed SMEM, then all
// chunk edges computed back-to-back with zero DRAM latency in the loop.
__global__ __launch_bounds__(256) void compute_kernel(
    const float* __restrict__ x,      // [E, 128]
    const float* __restrict__ Wpool,  // [P, 64, 128]
    const float* __restrict__ bpool,  // [P, 64]
    float* __restrict__ out)          // [E, 64]
{
    int w = blockIdx.x;
    int cnt = g_counts[w];
    if (cnt == 0) return;

    int tid = threadIdx.x;
    int r = tid >> 2;   // output row 0..63
    int q = tid & 3;    // K quadrant

    // W slice: 8 contiguous float4 per thread, fully coalesced warp-wise.
    const float4* Wg = reinterpret_cast<const float4*>(Wpool + (size_t)w * (OUT_DIM * IN_DIM));
    float4 wv[8];
    #pragma unroll
    for (int i = 0; i < 8; i++)
        wv[i] = Wg[r * 32 + q * 8 + i];

    float bias = bpool[(size_t)w * OUT_DIM + r];
    int start = g_offsets[w];

    __shared__ float sx[CHUNK][XROW];   // skewed: x[k] at [c][(k>>5)*36 + (k&31)]
    __shared__ int   se[CHUNK];

    for (int base = 0; base < cnt; base += CHUNK) {
        int nch = min(CHUNK, cnt - base);
        __syncthreads();                              // protect previous chunk
        if (tid < nch) se[tid] = g_sorted[start + base + tid];
        __syncthreads();

        // Coalesced x prefetch: thread tid loads float4 #(tid&31) of edge slot tid>>5.
        {
            int c = tid >> 5;
            int p = tid & 31;            // float4 index: covers x words 4p..4p+3
            if (c < nch) {
                float4 v = reinterpret_cast<const float4*>(x)[(size_t)se[c] * 32 + p];
                int word = (p >> 3) * 36 + ((p & 7) << 2);   // skewed slot, 16B aligned
                *reinterpret_cast<float4*>(&sx[c][word]) = v;
            }
        }
        __syncthreads();

        for (int c = 0; c < nch; c++) {
            const float* xs = &sx[c][q * 36];
            float a0 = 0.f, a1 = 0.f, a2 = 0.f, a3 = 0.f;
            #pragma unroll
            for (int i = 0; i < 8; i++) {
                float4 xv = *reinterpret_cast<const float4*>(&xs[4 * i]);
                a0 = fmaf(wv[i].x, xv.x, a0);
                a1 = fmaf(wv[i].y, xv.y, a1);
                a2 = fmaf(wv[i].z, xv.z, a2);
                a3 = fmaf(wv[i].w, xv.w, a3);
            }
            float acc = (a0 + a1) + (a2 + a3);
            acc += __shfl_xor_sync(0xffffffffu, acc, 1);
            acc += __shfl_xor_sync(0xffffffffu, acc, 2);
            if (q == 0) {
                float y = acc + bias;
                out[(size_t)se[c] * OUT_DIM + r] = y > 0.f ? y : 0.f;
            }
        }
    }
}

// ---------------------------------------------------------------------------
extern "C" void kernel_launch(void* const* d_in, const int* in_sizes, int n_in,
                              void* d_out, int out_size) {
    const float* x     = (const float*)d_in[0];  // [E,128,1]
    const int*   idx   = (const int*)d_in[1];    // [E]
    const float* Wpool = (const float*)d_in[2];  // [P,64,128]
    const float* bpool = (const float*)d_in[3];  // [P,64,1]
    float* out = (float*)d_out;                  // [E,64,1]

    int E     = in_sizes[1];
    int npool = in_sizes[3] / OUT_DIM;

    int eb = (E + 255) / 256;
    int pb = (npool + 255) / 256;

    zero_counts_kernel<<<pb, 256>>>(npool);
    hist_kernel<<<eb, 256>>>(idx, E);
    scan_kernel<<<1, 1024>>>(npool);
    scatter_kernel<<<eb, 256>>>(idx, E);
    compute_kernel<<<npool, 256>>>(x, Wpool, bpool, out);
}